// round 2
// baseline (speedup 1.0000x reference)
#include <cuda_runtime.h>
#include <math.h>

#define BB 16
#define CC 256
#define HH 64
#define WW 64
#define KK 4
#define OO 256
#define HID 65
#define TEMP 34.0f

// scratch (static __device__ allocations are allowed)
__device__ float g_pooled[BB*CC];
__device__ float g_att[BB*KK];
__device__ float g_aggw[BB*OO*CC*9];   // ~37.7 MB

// ---------------------------------------------------------------------------
// Kernel 1: global average pool  -> g_pooled[b*C + c]
// ---------------------------------------------------------------------------
__global__ void pool_kernel(const float* __restrict__ x) {
    int bc = blockIdx.x;                       // b*C + c
    const float* p = x + (size_t)bc * (HH*WW);
    float s = 0.f;
    for (int i = threadIdx.x; i < HH*WW; i += blockDim.x) s += p[i];
    __shared__ float red[128];
    red[threadIdx.x] = s;
    __syncthreads();
    for (int off = 64; off > 0; off >>= 1) {
        if (threadIdx.x < off) red[threadIdx.x] += red[threadIdx.x + off];
        __syncthreads();
    }
    if (threadIdx.x == 0) g_pooled[bc] = red[0] * (1.0f/(HH*WW));
}

// ---------------------------------------------------------------------------
// Kernel 2: MLP + softmax(logits/T)  -> g_att[b*K + k]
// ---------------------------------------------------------------------------
__global__ void att_kernel(const float* __restrict__ w_fc1,
                           const float* __restrict__ w_fc2,
                           const float* __restrict__ b_fc2) {
    __shared__ float pooled_s[BB*CC];
    __shared__ float h_s[BB][HID];
    __shared__ float logits_s[BB][KK];
    int tid = threadIdx.x;
    for (int i = tid; i < BB*CC; i += blockDim.x) pooled_s[i] = g_pooled[i];
    __syncthreads();
    for (int t = tid; t < BB*HID; t += blockDim.x) {
        int b = t / HID, j = t - b*HID;
        float acc = 0.f;
        const float* wr = w_fc1 + j*CC;
        const float* pr = pooled_s + b*CC;
        #pragma unroll 4
        for (int c = 0; c < CC; c++) acc += pr[c]*wr[c];
        h_s[b][j] = fmaxf(acc, 0.f);
    }
    __syncthreads();
    if (tid < BB*KK) {
        int b = tid / KK, k = tid - b*KK;
        float acc = b_fc2[k];
        const float* wr = w_fc2 + k*HID;
        for (int j = 0; j < HID; j++) acc += h_s[b][j]*wr[j];
        logits_s[b][k] = acc * (1.0f/TEMP);
    }
    __syncthreads();
    if (tid < BB) {
        int b = tid;
        float m = logits_s[b][0];
        #pragma unroll
        for (int k = 1; k < KK; k++) m = fmaxf(m, logits_s[b][k]);
        float e[KK]; float s = 0.f;
        #pragma unroll
        for (int k = 0; k < KK; k++) { e[k] = expf(logits_s[b][k] - m); s += e[k]; }
        float inv = 1.0f / s;
        #pragma unroll
        for (int k = 0; k < KK; k++) g_att[b*KK + k] = e[k] * inv;
    }
}

// ---------------------------------------------------------------------------
// Kernel 3: aggregate weights  agg_w[b] = sum_k att[b,k] * W[k]
// base weight (9.4MB) stays L2-resident across the 4 strided reads.
// ---------------------------------------------------------------------------
__global__ void aggw_kernel(const float* __restrict__ wt) {
    const int per = OO*CC*9;                   // 589824
    const int n = BB*per;
    for (int m = blockIdx.x*blockDim.x + threadIdx.x; m < n;
         m += gridDim.x*blockDim.x) {
        int b = m / per;
        int r = m - b*per;
        float a0 = g_att[b*4+0], a1 = g_att[b*4+1];
        float a2 = g_att[b*4+2], a3 = g_att[b*4+3];
        g_aggw[m] = a0*wt[r] + a1*wt[per + r] + a2*wt[2*per + r] + a3*wt[3*per + r];
    }
}

// ---------------------------------------------------------------------------
// Kernel 4: direct 3x3 conv, per-sample aggregated weights, fused agg_b.
// Block: 32 O x (16x16) spatial, thread: 4 O x 8 px, C chunked by 8.
// ---------------------------------------------------------------------------
__global__ __launch_bounds__(256, 2)
void conv_kernel(const float* __restrict__ x,
                 const float* __restrict__ bias,
                 float* __restrict__ out) {
    __shared__ float x_s[8][18][18];   // input tile + halo
    __shared__ float w_s[32*72];       // [o][c*9+rs] for 32 O x 8 C x 9

    const int tid  = threadIdx.x;
    const int b    = blockIdx.z;
    const int o0   = blockIdx.y * 32;
    const int t    = blockIdx.x;               // 0..15 -> 4x4 spatial tiles
    const int y0   = (t >> 2) * 16;
    const int x0   = (t & 3)  * 16;
    const int osub = (tid >> 5) * 4;           // 0,4,...,28
    const int pg   = tid & 31;
    const int rloc = pg >> 1;                  // 0..15 (row within tile)
    const int cb   = (pg & 1) * 8;             // 0 or 8 (col base)

    float acc[4][8];
    #pragma unroll
    for (int oo = 0; oo < 4; oo++)
        #pragma unroll
        for (int i = 0; i < 8; i++) acc[oo][i] = 0.f;

    const float* xb = x + (size_t)(b*CC) * (HH*WW);
    const float* wb = g_aggw + (size_t)((b*OO + o0)*CC) * 9;

    for (int c0 = 0; c0 < CC; c0 += 8) {
        __syncthreads();
        // ---- load x tile (18x18 halo, zero-pad borders) ----
        for (int e = tid; e < 8*18*18; e += 256) {
            int c   = e / 324;
            int rem = e - c*324;
            int yy  = rem / 18;
            int xx  = rem - yy*18;
            int gy  = y0 - 1 + yy;
            int gx  = x0 - 1 + xx;
            float v = 0.f;
            if ((unsigned)gy < 64u && (unsigned)gx < 64u)
                v = xb[(size_t)(c0 + c)*4096 + gy*64 + gx];
            x_s[c][yy][xx] = v;
        }
        // ---- load aggregated weight tile ----
        const float* wbc = wb + c0*9;
        for (int e = tid; e < 2304; e += 256) {
            int o   = e / 72;
            int off = e - o*72;                // c*9 + rs
            w_s[e] = wbc[o*(CC*9) + off];
        }
        __syncthreads();

        // ---- compute ----
        #pragma unroll 2
        for (int cc = 0; cc < 8; cc++) {
            #pragma unroll
            for (int r = 0; r < 3; r++) {
                float xv[10];
                const float* xr = &x_s[cc][rloc + r][cb];
                #pragma unroll
                for (int i = 0; i < 10; i++) xv[i] = xr[i];
                const float* wp = &w_s[osub*72 + cc*9 + r*3];
                #pragma unroll
                for (int oo = 0; oo < 4; oo++) {
                    float w0 = wp[oo*72 + 0];
                    float w1 = wp[oo*72 + 1];
                    float w2 = wp[oo*72 + 2];
                    #pragma unroll
                    for (int i = 0; i < 8; i++)
                        acc[oo][i] += w0*xv[i] + w1*xv[i+1] + w2*xv[i+2];
                }
            }
        }
    }

    // ---- epilogue: + agg_b, store ----
    float a0 = g_att[b*4+0], a1 = g_att[b*4+1];
    float a2 = g_att[b*4+2], a3 = g_att[b*4+3];
    #pragma unroll
    for (int oo = 0; oo < 4; oo++) {
        int o = o0 + osub + oo;
        float ab = a0*bias[o] + a1*bias[OO + o] + a2*bias[2*OO + o] + a3*bias[3*OO + o];
        float* op = out + (size_t)(b*OO + o)*4096 + (y0 + rloc)*64 + x0 + cb;
        #pragma unroll
        for (int i = 0; i < 8; i++) op[i] = acc[oo][i] + ab;
    }
}

// ---------------------------------------------------------------------------
extern "C" void kernel_launch(void* const* d_in, const int* in_sizes, int n_in,
                              void* d_out, int out_size) {
    const float* x     = (const float*)d_in[0];
    const float* w_fc1 = (const float*)d_in[1];
    const float* w_fc2 = (const float*)d_in[2];
    const float* b_fc2 = (const float*)d_in[3];
    const float* wt    = (const float*)d_in[4];
    const float* bias  = (const float*)d_in[5];
    float* out = (float*)d_out;

    pool_kernel<<<BB*CC, 128>>>(x);
    att_kernel<<<1, 1024>>>(w_fc1, w_fc2, b_fc2);
    aggw_kernel<<<4608, 256>>>(wt);
    conv_kernel<<<dim3(16, 8, 16), 256>>>(x, bias, out);
}